// round 8
// baseline (speedup 1.0000x reference)
#include <cuda_runtime.h>
#include <cuda_bf16.h>
#include <math.h>

// ---------------------------------------------------------------------------
// CompactHash — R8: R7 with the resScale bug fixed (2^4 = 16, not 256).
//  2 warps per point; warp half h handles levels 4h..4h+3.
//  lane = (corner_xy[2b], pp[3b]); each lane serves corners (bx,by,0/1).
//  v[8] accumulators -> lower reg pressure -> 5 blocks/SM target.
//  Epilogue: 3-stage multi-value butterfly + 2 reduce shuffles (9 SHFL).
// ---------------------------------------------------------------------------

#define NUM_LEVELS   8
#define PROBE        16
#define INDEX_PARAMS 16384
#define TOTAL_CB_ROWS (NUM_LEVELS * INDEX_PARAMS)   // 131072
#define BATCH        524288

// 8 MB scratch for normalized codebook (device global: no allocation APIs).
__device__ float g_cbnorm[TOTAL_CB_ROWS * PROBE];

__constant__ int c_level_off[NUM_LEVELS] =
    {0, 4096, 36864, 299008, 823296, 1347584, 1871872, 2396160};

// -------------------------------- softmax prologue -------------------------
__global__ void __launch_bounds__(256)
softmax_cb_kernel(const float* __restrict__ cb)
{
    int row = blockIdx.x * blockDim.x + threadIdx.x;   // 0 .. 131071
    const float4* src = reinterpret_cast<const float4*>(cb + (size_t)row * PROBE);
    float4 v0 = __ldg(src + 0);
    float4 v1 = __ldg(src + 1);
    float4 v2 = __ldg(src + 2);
    float4 v3 = __ldg(src + 3);

    float e[16];
    // codebook values are tiny (|x| < 0.01): no max-subtraction needed.
    e[0]  = __expf(v0.x); e[1]  = __expf(v0.y); e[2]  = __expf(v0.z); e[3]  = __expf(v0.w);
    e[4]  = __expf(v1.x); e[5]  = __expf(v1.y); e[6]  = __expf(v1.z); e[7]  = __expf(v1.w);
    e[8]  = __expf(v2.x); e[9]  = __expf(v2.y); e[10] = __expf(v2.z); e[11] = __expf(v2.w);
    e[12] = __expf(v3.x); e[13] = __expf(v3.y); e[14] = __expf(v3.z); e[15] = __expf(v3.w);

    float s = 0.f;
#pragma unroll
    for (int i = 0; i < 16; i++) s += e[i];
    float inv = __fdividef(1.f, s);

    float4* dst = reinterpret_cast<float4*>(g_cbnorm + (size_t)row * PROBE);
    dst[0] = make_float4(e[0]*inv,  e[1]*inv,  e[2]*inv,  e[3]*inv);
    dst[1] = make_float4(e[4]*inv,  e[5]*inv,  e[6]*inv,  e[7]*inv);
    dst[2] = make_float4(e[8]*inv,  e[9]*inv,  e[10]*inv, e[11]*inv);
    dst[3] = make_float4(e[12]*inv, e[13]*inv, e[14]*inv, e[15]*inv);
}

// -------------------------------- main kernel ------------------------------
__global__ void __launch_bounds__(256, 5)
compact_hash_kernel(const float*  __restrict__ inp,   // [BATCH,3]
                    const float2* __restrict__ emb,   // [TOTAL_EMB] rows of 2
                    float*        __restrict__ out)   // [BATCH,16]
{
    const int gw    = (blockIdx.x * blockDim.x + threadIdx.x) >> 5;
    const int point = gw >> 1;          // point id
    const int half  = gw & 1;           // which 4 levels
    const int lane  = threadIdx.x & 31;
    const unsigned bx = (lane >> 3) & 1;
    const unsigned by = (lane >> 4) & 1;
    const int      pp = lane & 7;       // probe pair (rows 2pp, 2pp+1)

    const float px = __ldg(inp + point * 3 + 0);
    const float py = __ldg(inp + point * 3 + 1);
    const float pz = __ldg(inp + point * 3 + 2);

    const int   Lb       = half << 2;                  // base level
    const float resScale = half ? 16.f : 1.f;          // 2^(4*half)  (FIXED)

    float v[8];   // v[2i] = comp0 of level Lb+i, v[2i+1] = comp1
#pragma unroll
    for (int i = 0; i < 8; i++) v[i] = 0.f;

    const unsigned pmlo[4] = {(1u<<12)-1u, (1u<<15)-1u, (1u<<18)-1u, (1u<<19)-1u};

#pragma unroll
    for (int i = 0; i < 4; i++) {
        const float    res = (float)(16 << i) * resScale;
        const unsigned pm  = half ? ((1u<<19)-1u) : pmlo[i];

        const float fx = px * res, fy = py * res, fz = pz * res;
        const float ix = floorf(fx), iy = floorf(fy), iz = floorf(fz);
        const float xf = fx - ix,    yf = fy - iy,    zf = fz - iz;

        // hashes for both corners (prime for dim 0 is 1)
        const unsigned xs  = (unsigned)(int)ix + bx;
        const unsigned yb  = (unsigned)(int)iy + by;
        const unsigned ym1 = yb * 2654435761u;
        const unsigned ym2 = yb * 2654435767u;
        const unsigned zm1 = (unsigned)(int)iz * 805459861u;
        const unsigned zm2 = (unsigned)(int)iz * 805459871u;
        const unsigned ha  = xs ^ ym1;
        const unsigned hb  = xs ^ ym2;
        const unsigned h1a = ha ^ zm1;                  // bz = 0
        const unsigned h1b = ha ^ (zm1 + 805459861u);   // bz = 1
        const unsigned h2a = hb ^ zm2;
        const unsigned h2b = hb ^ (zm2 + 805459871u);

        const unsigned baseA = (h1a << 4) & pm;
        const unsigned baseB = (h1b << 4) & pm;
        const unsigned crA   = h2a & (INDEX_PARAMS - 1u);
        const unsigned crB   = h2b & (INDEX_PARAMS - 1u);

        // trilinear weights
        const float wxy = (bx ? xf : 1.f - xf) * (by ? yf : 1.f - yf);
        const float wtA = wxy * (1.f - zf);
        const float wtB = wxy * zf;

        const float4* __restrict__ embL =
            reinterpret_cast<const float4*>(emb + c_level_off[Lb + i]);
        const float2* __restrict__ cbL =
            reinterpret_cast<const float2*>(g_cbnorm)
            + ((size_t)(Lb + i) << 17) + pp;

        // corner A (bz=0): 8 lanes cover the full 128B emb line
        const float4 ea = __ldg(embL + (baseA >> 1) + pp);
        const float2 wa = __ldg(cbL + crA * (PROBE / 2));
        // corner B (bz=1)
        const float4 eb = __ldg(embL + (baseB >> 1) + pp);
        const float2 wb = __ldg(cbL + crB * (PROBE / 2));

        float sa0 = wa.x * ea.x;
        float sa1 = wa.x * ea.y;
        sa0 = fmaf(wa.y, ea.z, sa0);
        sa1 = fmaf(wa.y, ea.w, sa1);
        float sb0 = wb.x * eb.x;
        float sb1 = wb.x * eb.y;
        sb0 = fmaf(wb.y, eb.z, sb0);
        sb1 = fmaf(wb.y, eb.w, sb1);

        v[2*i]   = fmaf(wtA, sa0, fmaf(wtB, sb0, v[2*i]));
        v[2*i+1] = fmaf(wtA, sa1, fmaf(wtB, sb1, v[2*i+1]));
    }

    // ---- multi-value butterfly: 8 values over 32 lanes ----
    // Route value-bit b to lane-bit b (masks 1,2,4), then reduce lane-bits
    // 8 and 16. Afterwards lane l holds feature (l & 7) summed over lanes.
    float t4[4];
#pragma unroll
    for (int k = 0; k < 4; k++) {
        const float lo = v[2*k], hi = v[2*k+1];
        const float send = (lane & 1) ? lo : hi;
        const float recv = __shfl_xor_sync(0xffffffffu, send, 1);
        t4[k] = ((lane & 1) ? hi : lo) + recv;
    }
    float t2[2];
#pragma unroll
    for (int k = 0; k < 2; k++) {
        const float lo = t4[2*k], hi = t4[2*k+1];
        const float send = (lane & 2) ? lo : hi;
        const float recv = __shfl_xor_sync(0xffffffffu, send, 2);
        t2[k] = ((lane & 2) ? hi : lo) + recv;
    }
    float t1;
    {
        const float lo = t2[0], hi = t2[1];
        const float send = (lane & 4) ? lo : hi;
        const float recv = __shfl_xor_sync(0xffffffffu, send, 4);
        t1 = ((lane & 4) ? hi : lo) + recv;
    }
    t1 += __shfl_xor_sync(0xffffffffu, t1, 8);
    t1 += __shfl_xor_sync(0xffffffffu, t1, 16);

    // warp half h writes features 8h .. 8h+7 of its point
    if (lane < 8) out[(size_t)point * 16 + half * 8 + lane] = t1;
}

// -------------------------------- launcher ---------------------------------
extern "C" void kernel_launch(void* const* d_in, const int* in_sizes, int n_in,
                              void* d_out, int out_size)
{
    const float*  inputs     = (const float*)d_in[0];   // [524288, 3]
    const float2* embeddings = (const float2*)d_in[1];  // [2920448, 2]
    const float*  code_book  = (const float*)d_in[2];   // [131072, 16]
    float*        out        = (float*)d_out;           // [524288, 16]

    softmax_cb_kernel<<<TOTAL_CB_ROWS / 256, 256>>>(code_book);
    // 2 warps per point -> 1048576 warps -> 131072 blocks of 8 warps
    compact_hash_kernel<<<(BATCH * 2) / 8, 256>>>(inputs, embeddings, out);
}

// round 10
// speedup vs baseline: 1.1613x; 1.1613x over previous
#include <cuda_runtime.h>
#include <cuda_bf16.h>
#include <math.h>

// ---------------------------------------------------------------------------
// CompactHash — R9 (resubmit): R6 16-wf/level layout, single warp per point,
//  + reg cap (48) for occupancy, constexpr-immediate level offsets,
//  + flat 32-bit offset addressing, grouped loads (MLP=4).
//  lane = (corner_xy[2b], probe_pair[3b]); each lane serves corners
//  (bx,by,0) and (bx,by,1). 16 L1 wavefronts per level (fp32 floor).
// ---------------------------------------------------------------------------

#define NUM_LEVELS   8
#define PROBE        16
#define INDEX_PARAMS 16384
#define TOTAL_CB_ROWS (NUM_LEVELS * INDEX_PARAMS)   // 131072
#define BATCH        524288

// 8 MB scratch for normalized codebook (device global: no allocation APIs).
__device__ float g_cbnorm[TOTAL_CB_ROWS * PROBE];

// -------------------------------- softmax prologue -------------------------
__global__ void __launch_bounds__(256)
softmax_cb_kernel(const float* __restrict__ cb)
{
    int row = blockIdx.x * blockDim.x + threadIdx.x;   // 0 .. 131071
    const float4* src = reinterpret_cast<const float4*>(cb + (size_t)row * PROBE);
    float4 v0 = __ldg(src + 0);
    float4 v1 = __ldg(src + 1);
    float4 v2 = __ldg(src + 2);
    float4 v3 = __ldg(src + 3);

    float e[16];
    // codebook values are tiny (|x| < 0.01): no max-subtraction needed.
    e[0]  = __expf(v0.x); e[1]  = __expf(v0.y); e[2]  = __expf(v0.z); e[3]  = __expf(v0.w);
    e[4]  = __expf(v1.x); e[5]  = __expf(v1.y); e[6]  = __expf(v1.z); e[7]  = __expf(v1.w);
    e[8]  = __expf(v2.x); e[9]  = __expf(v2.y); e[10] = __expf(v2.z); e[11] = __expf(v2.w);
    e[12] = __expf(v3.x); e[13] = __expf(v3.y); e[14] = __expf(v3.z); e[15] = __expf(v3.w);

    float s = 0.f;
#pragma unroll
    for (int i = 0; i < 16; i++) s += e[i];
    float inv = __fdividef(1.f, s);

    float4* dst = reinterpret_cast<float4*>(g_cbnorm + (size_t)row * PROBE);
    dst[0] = make_float4(e[0]*inv,  e[1]*inv,  e[2]*inv,  e[3]*inv);
    dst[1] = make_float4(e[4]*inv,  e[5]*inv,  e[6]*inv,  e[7]*inv);
    dst[2] = make_float4(e[8]*inv,  e[9]*inv,  e[10]*inv, e[11]*inv);
    dst[3] = make_float4(e[12]*inv, e[13]*inv, e[14]*inv, e[15]*inv);
}

// -------------------------------- main kernel ------------------------------
__global__ void __launch_bounds__(256, 5)
compact_hash_kernel(const float*  __restrict__ inp,   // [BATCH,3]
                    const float4* __restrict__ emb4,  // emb as float4 (2 rows)
                    float*        __restrict__ out)   // [BATCH,16]
{
    // level row-offsets (compile-time immediates after unroll)
    constexpr unsigned LOFF[NUM_LEVELS] =
        {0, 4096, 36864, 299008, 823296, 1347584, 1871872, 2396160};
    constexpr unsigned LBITS[NUM_LEVELS] = {12, 15, 18, 19, 19, 19, 19, 19};

    const int warp = (blockIdx.x * blockDim.x + threadIdx.x) >> 5;  // point id
    const int lane = threadIdx.x & 31;
    const unsigned bx = (lane >> 3) & 1;   // corner x-bit (shared by corners)
    const unsigned by = (lane >> 4) & 1;   // corner y-bit (shared)
    const unsigned pp = lane & 7;          // probe pair (rows 2pp, 2pp+1)

    const float px = __ldg(inp + warp * 3 + 0);
    const float py = __ldg(inp + warp * 3 + 1);
    const float pz = __ldg(inp + warp * 3 + 2);

    const float2* __restrict__ cb2 = reinterpret_cast<const float2*>(g_cbnorm);

    float v[16];   // v[2L] = comp0 partial of level L, v[2L+1] = comp1
#pragma unroll
    for (int i = 0; i < 16; i++) v[i] = 0.f;

#pragma unroll
    for (int L = 0; L < NUM_LEVELS; L++) {
        const float    res = (float)(16 << L);
        const unsigned pm  = (1u << LBITS[L]) - 1u;

        const float fx = px * res, fy = py * res, fz = pz * res;
        const float ix = floorf(fx), iy = floorf(fy), iz = floorf(fz);
        const float xf = fx - ix,    yf = fy - iy,    zf = fz - iz;

        // hashes for both corners (prime for dim 0 is 1)
        const unsigned xs  = (unsigned)(int)ix + bx;
        const unsigned yb  = (unsigned)(int)iy + by;
        const unsigned ha  = xs ^ (yb * 2654435761u);
        const unsigned hb  = xs ^ (yb * 2654435767u);
        const unsigned zm1 = (unsigned)(int)iz * 805459861u;
        const unsigned zm2 = (unsigned)(int)iz * 805459871u;
        const unsigned h1a = ha ^ zm1;                   // bz = 0
        const unsigned h1b = ha ^ (zm1 + 805459861u);    // bz = 1
        const unsigned h2a = hb ^ zm2;
        const unsigned h2b = hb ^ (zm2 + 805459871u);

        // flat 32-bit element offsets
        const unsigned offA = ((LOFF[L] + ((h1a << 4) & pm)) >> 1) + pp; // float4
        const unsigned offB = ((LOFF[L] + ((h1b << 4) & pm)) >> 1) + pp;
        const unsigned cbA  = ((unsigned)(L << 14) + (h2a & (INDEX_PARAMS-1u))) * 8u + pp; // float2
        const unsigned cbB  = ((unsigned)(L << 14) + (h2b & (INDEX_PARAMS-1u))) * 8u + pp;

        // grouped gathers (MLP = 4)
        const float4 ea = __ldg(emb4 + offA);
        const float4 eb = __ldg(emb4 + offB);
        const float2 wa = __ldg(cb2 + cbA);
        const float2 wb = __ldg(cb2 + cbB);

        // trilinear weights
        const float wxy = (bx ? xf : 1.f - xf) * (by ? yf : 1.f - yf);
        const float wtA = wxy * (1.f - zf);
        const float wtB = wxy * zf;

        float sa0 = wa.x * ea.x;
        float sa1 = wa.x * ea.y;
        sa0 = fmaf(wa.y, ea.z, sa0);
        sa1 = fmaf(wa.y, ea.w, sa1);
        float sb0 = wb.x * eb.x;
        float sb1 = wb.x * eb.y;
        sb0 = fmaf(wb.y, eb.z, sb0);
        sb1 = fmaf(wb.y, eb.w, sb1);

        v[2*L]   = fmaf(wtA, sa0, fmaf(wtB, sb0, v[2*L]));
        v[2*L+1] = fmaf(wtA, sa1, fmaf(wtB, sb1, v[2*L+1]));
    }

    // ---- multi-value butterfly reduction: 16 values over 32 lanes ----
    // Stages route value-bit b to lane-bit b (masks 1,2,4,8), then mask 16
    // final-reduces. Afterwards lane l holds feature (l & 15) summed over
    // all 32 lanes.
    float t8[8];
#pragma unroll
    for (int k = 0; k < 8; k++) {
        const float lo = v[2*k], hi = v[2*k+1];
        const float send = (lane & 1) ? lo : hi;
        const float recv = __shfl_xor_sync(0xffffffffu, send, 1);
        t8[k] = ((lane & 1) ? hi : lo) + recv;
    }
    float t4[4];
#pragma unroll
    for (int k = 0; k < 4; k++) {
        const float lo = t8[2*k], hi = t8[2*k+1];
        const float send = (lane & 2) ? lo : hi;
        const float recv = __shfl_xor_sync(0xffffffffu, send, 2);
        t4[k] = ((lane & 2) ? hi : lo) + recv;
    }
    float t2[2];
#pragma unroll
    for (int k = 0; k < 2; k++) {
        const float lo = t4[2*k], hi = t4[2*k+1];
        const float send = (lane & 4) ? lo : hi;
        const float recv = __shfl_xor_sync(0xffffffffu, send, 4);
        t2[k] = ((lane & 4) ? hi : lo) + recv;
    }
    float t1;
    {
        const float lo = t2[0], hi = t2[1];
        const float send = (lane & 8) ? lo : hi;
        const float recv = __shfl_xor_sync(0xffffffffu, send, 8);
        t1 = ((lane & 8) ? hi : lo) + recv;
    }
    const float r = t1 + __shfl_xor_sync(0xffffffffu, t1, 16);

    if (lane < 16) out[(size_t)warp * 16 + lane] = r;
}

// -------------------------------- launcher ---------------------------------
extern "C" void kernel_launch(void* const* d_in, const int* in_sizes, int n_in,
                              void* d_out, int out_size)
{
    const float*  inputs     = (const float*)d_in[0];   // [524288, 3]
    const float4* embeddings = (const float4*)d_in[1];  // [2920448/2] float4
    const float*  code_book  = (const float*)d_in[2];   // [131072, 16]
    float*        out        = (float*)d_out;           // [524288, 16]

    softmax_cb_kernel<<<TOTAL_CB_ROWS / 256, 256>>>(code_book);
    compact_hash_kernel<<<BATCH / 8, 256>>>(inputs, embeddings, out);
}